// round 15
// baseline (speedup 1.0000x reference)
#include <cuda_runtime.h>

// Depthwise 3x3 conv with hard-one-hot kernel == pure spatial shift, zero pad:
//   out[b,c,h,w] = x[b,c, h+dy, w+dx],  (dy,dx) = argmax(|weight|) - 1
//
// One warp per TWO image rows, processed sequentially (keeps regs ~R2-level
// so 1024-thread blocks still get 2 resident blocks/SM). Row pair: gw and
// gw + nrows/2 (same h -> warp-uniform bounds branch, shared shift logic).
// Per row: 2 aligned float4 per lane, +-1 horizontal shift via one register
// shuffle (value shuffled past lane 0/31 is exactly the zero padding).
// Grid: 4096 blocks of 1024 threads — block-count term minimized.

#define NROWS_HALF 131072   // (16*64*256*256 / 256) / 2

__device__ __forceinline__ void shift_row(
    const float4 r0, const float4 r1, int dx, int lane,
    float4& o0, float4& o1)
{
    if (dx == 0) {
        o0 = r0; o1 = r1;
    } else if (dx > 0) {
        float nxt = __shfl_down_sync(0xffffffffu, r0.x, 1);
        if (lane == 31) nxt = 0.0f;            // col 256 -> zero pad
        o0 = make_float4(r0.y, r0.z, r0.w, r1.x);
        o1 = make_float4(r1.y, r1.z, r1.w, nxt);
    } else {
        float prv = __shfl_up_sync(0xffffffffu, r1.w, 1);
        if (lane == 0) prv = 0.0f;             // col -1 -> zero pad
        o0 = make_float4(prv, r0.x, r0.y, r0.z);
        o1 = make_float4(r0.w, r1.x, r1.y, r1.z);
    }
}

__global__ __launch_bounds__(1024) void shift_row2s_kernel(
    const float* __restrict__ x, const float* __restrict__ w9,
    float* __restrict__ out)
{
    __shared__ int2 s_shift;
    if (threadIdx.x == 0) {
        float best = -1.0f;
        int bi = 0;
        #pragma unroll
        for (int i = 0; i < 9; ++i) {
            float a = fabsf(w9[i]);
            if (a > best) { best = a; bi = i; }   // first occurrence wins (jnp.argmax)
        }
        s_shift = make_int2(bi / 3 - 1, bi % 3 - 1);
    }
    __syncthreads();
    const int dy = s_shift.x;
    const int dx = s_shift.y;

    const int gw   = (blockIdx.x * blockDim.x + threadIdx.x) >> 5;  // row id A
    const int lane = threadIdx.x & 31;

    const int h  = gw & 255;                   // same for both rows
    const int sh = h + dy;
    const bool inb = ((unsigned)sh < 256u);    // warp-uniform

    const size_t planeA = (size_t)(gw >> 8);
    const size_t rowOffA = ((planeA << 8) + (size_t)sh) * 256;
    const size_t dstOffA = ((size_t)gw << 6) + (lane << 1);

    // ---- row A ----
    {
        float4 o0, o1;
        if (inb) {
            const float4* src = reinterpret_cast<const float4*>(x + rowOffA) + (lane << 1);
            float4 r0 = src[0];
            float4 r1 = src[1];
            shift_row(r0, r1, dx, lane, o0, o1);
        } else {
            o0 = make_float4(0.f, 0.f, 0.f, 0.f);
            o1 = o0;
        }
        float4* dst = reinterpret_cast<float4*>(out) + dstOffA;
        dst[0] = o0;
        dst[1] = o1;
    }

    // ---- row B (plane + NROWS_HALF/256, same h) ----
    {
        float4 o0, o1;
        if (inb) {
            const float4* src = reinterpret_cast<const float4*>(
                x + rowOffA + ((size_t)NROWS_HALF << 8)) + (lane << 1);
            float4 r0 = src[0];
            float4 r1 = src[1];
            shift_row(r0, r1, dx, lane, o0, o1);
        } else {
            o0 = make_float4(0.f, 0.f, 0.f, 0.f);
            o1 = o0;
        }
        float4* dst = reinterpret_cast<float4*>(out) + dstOffA + ((size_t)NROWS_HALF << 6);
        dst[0] = o0;
        dst[1] = o1;
    }
}

extern "C" void kernel_launch(void* const* d_in, const int* in_sizes, int n_in,
                              void* d_out, int out_size) {
    const float* x = (const float*)d_in[0];
    const float* w = (const float*)d_in[1];
    float* out = (float*)d_out;

    // warps = nrows/2 = 131072 ; 32 warps per 1024-thread block -> 4096 blocks
    int warps  = (out_size >> 8) >> 1;
    int blocks = warps >> 5;
    shift_row2s_kernel<<<blocks, 1024>>>(x, w, out);
}

// round 16
// speedup vs baseline: 1.0134x; 1.0134x over previous
#include <cuda_runtime.h>

// FINAL — session best (R14, 80.35us total / 76.3us kernel / 80.1% DRAM).
//
// Depthwise 3x3 conv with hard-one-hot kernel == pure spatial shift, zero pad:
//   out[b,c,h,w] = x[b,c, h+dy, w+dx],  (dy,dx) = argmax(|weight|) - 1
//
// One warp per image row (W=256 -> 2 aligned float4 per lane). Horizontal
// +-1 shift via one register shuffle; the value shuffled past lane 0/31 is
// exactly the zero padding. Argmax once per block via smem. 1024-thread
// blocks (8192 blocks) minimize launch/raster overhead while the kernel
// itself sits at the HBM mixed-stream ceiling (~6.35 TB/s on 536 MB moved).
// Probes measured neutral-or-worse: 2-row MLP batching, per-thread argmax,
// __ldcs/__stcs, v8 256-bit accesses, persistent single-wave grid,
// sequential 2-row blocks.

__global__ __launch_bounds__(1024) void shift_row_kernel(
    const float* __restrict__ x, const float* __restrict__ w9,
    float* __restrict__ out)
{
    __shared__ int2 s_shift;
    if (threadIdx.x == 0) {
        float best = -1.0f;
        int bi = 0;
        #pragma unroll
        for (int i = 0; i < 9; ++i) {
            float a = fabsf(w9[i]);
            if (a > best) { best = a; bi = i; }   // first occurrence wins (jnp.argmax)
        }
        s_shift = make_int2(bi / 3 - 1, bi % 3 - 1);
    }
    __syncthreads();
    const int dy = s_shift.x;
    const int dx = s_shift.y;

    const int gw   = (blockIdx.x * blockDim.x + threadIdx.x) >> 5;  // row id
    const int lane = threadIdx.x & 31;

    const int h  = gw & 255;                   // row within plane
    const int sh = h + dy;
    const size_t plane = (size_t)(gw >> 8);    // fused b*c plane

    float4 o0, o1;
    if ((unsigned)sh < 256u) {                 // warp-uniform
        const float4* src = reinterpret_cast<const float4*>(
            x + ((plane << 8) + (size_t)sh) * 256) + (lane << 1);
        float4 r0 = src[0];
        float4 r1 = src[1];
        if (dx == 0) {
            o0 = r0; o1 = r1;
        } else if (dx > 0) {
            float nxt = __shfl_down_sync(0xffffffffu, r0.x, 1);
            if (lane == 31) nxt = 0.0f;        // col 256 -> zero pad
            o0 = make_float4(r0.y, r0.z, r0.w, r1.x);
            o1 = make_float4(r1.y, r1.z, r1.w, nxt);
        } else {
            float prv = __shfl_up_sync(0xffffffffu, r1.w, 1);
            if (lane == 0) prv = 0.0f;         // col -1 -> zero pad
            o0 = make_float4(prv, r0.x, r0.y, r0.z);
            o1 = make_float4(r0.w, r1.x, r1.y, r1.z);
        }
    } else {
        o0 = make_float4(0.f, 0.f, 0.f, 0.f);
        o1 = o0;
    }

    float4* dst = reinterpret_cast<float4*>(out) + ((size_t)gw << 6) + (lane << 1);
    dst[0] = o0;
    dst[1] = o1;
}

extern "C" void kernel_launch(void* const* d_in, const int* in_sizes, int n_in,
                              void* d_out, int out_size) {
    const float* x = (const float*)d_in[0];
    const float* w = (const float*)d_in[1];
    float* out = (float*)d_out;

    int nrows  = out_size >> 8;     // 262144 rows
    int blocks = nrows >> 5;        // 32 warps (rows) per 1024-thread block
    shift_row_kernel<<<blocks, 1024>>>(x, w, out);
}